// round 1
// baseline (speedup 1.0000x reference)
#include <cuda_runtime.h>
#include <math.h>

#define B 32
#define L 256
#define EXT 64
#define H 256
#define M 64
#define NMEM 4096
#define NST 32
#define OUT 64

// ---------------- scratch (device globals; no allocation) ----------------
__device__ float g_xm[B * H];
__device__ float g_kw[B * M], g_e[B * M], g_a[B * M], g_kr[B * M];
__device__ float g_pw[B * 8], g_pr[B * 8];   // [beta, g, s0, s1, s2, gamma, knorm, pad]
__device__ float g_score[B * NMEM];
__device__ float g_ww[B * NMEM], g_wr[B * NMEM];
__device__ float g_rpart[B * 16 * M];

// ---------------- helpers ----------------
__device__ __forceinline__ float wredsum(float v) {
    #pragma unroll
    for (int o = 16; o > 0; o >>= 1) v += __shfl_xor_sync(0xffffffffu, v, o);
    return v;
}
__device__ __forceinline__ float wredmax(float v) {
    #pragma unroll
    for (int o = 16; o > 0; o >>= 1) v = fmaxf(v, __shfl_xor_sync(0xffffffffu, v, o));
    return v;
}
__device__ __forceinline__ float softplus_f(float x) {
    return (x > 20.f) ? x : log1pf(expf(x));
}
__device__ __forceinline__ float sigmoid_f(float x) {
    return 1.f / (1.f + expf(-x));
}

// ============ Kernel 1: encoder GEMM + S4D scan + temporal mean ============
// grid (B, H/8), block 256 (8 warps, warp w handles h = blockIdx.y*8 + w, lane = state n)
__global__ void k_encode_scan(
    const float* __restrict__ x, const float* __restrict__ r0,
    const float* __restrict__ sr0, const float* __restrict__ si0,
    const float* __restrict__ encW, const float* __restrict__ encb,
    const float* __restrict__ log_dt, const float* __restrict__ logAr,
    const float* __restrict__ Aim, const float* __restrict__ Cre,
    const float* __restrict__ Cim, const float* __restrict__ Dv)
{
    __shared__ float xs[64 * 65];    // L-chunk of x, padded to kill bank conflicts
    __shared__ float Wc[128 * 8];    // enc_W columns for this block's 8 heads
    __shared__ float us[8][64];      // u chunk per warp

    int b = blockIdx.x, hg = blockIdx.y;
    int t = threadIdx.x, w = t >> 5, lane = t & 31;
    int h = hg * 8 + w;

    for (int i = t; i < 128 * 8; i += 256) {
        int e = i >> 3, ww = i & 7;
        Wc[e * 8 + ww] = encW[e * H + hg * 8 + ww];
    }
    __syncthreads();

    // effective bias: enc_b[h] + r0[b,:] . enc_W[EXT:,h]
    float c = 0.f;
    #pragma unroll
    for (int m = lane; m < M; m += 32) c += r0[b * M + m] * Wc[(EXT + m) * 8 + w];
    c = wredsum(c) + encb[h];

    // per-lane S4D constants
    int n = lane;
    int idx = h * NST + n;
    float dt  = expf(log_dt[h]);
    float ar  = -expf(logAr[idx]);
    float ai  = Aim[idx];
    float er  = expf(dt * ar);
    float dAr = er * cosf(dt * ai);
    float dAi = er * sinf(dt * ai);
    float den = ar * ar + ai * ai;
    float numr = dAr - 1.f, numi = dAi;
    float dBr = (numr * ar + numi * ai) / den;
    float dBi = (numi * ar - numr * ai) / den;

    float sr = sr0[b * H * NST + idx], si = si0[b * H * NST + idx];
    float Sr = 0.f, Si = 0.f, usum = 0.f;

    for (int ch = 0; ch < 4; ch++) {
        __syncthreads();
        int l0 = ch * 64;
        for (int i = t; i < 64 * 64; i += 256) {
            int rr = i >> 6, cc = i & 63;
            xs[rr * 65 + cc] = x[((b * L) + (l0 + rr)) * EXT + cc];
        }
        __syncthreads();

        #pragma unroll
        for (int q = 0; q < 2; q++) {
            int ll = lane + q * 32;
            float acc = c;
            const float* xr = &xs[ll * 65];
            #pragma unroll 16
            for (int e = 0; e < EXT; e++) acc = fmaf(xr[e], Wc[e * 8 + w], acc);
            us[w][ll] = acc;
            usum += acc;
        }
        __syncwarp();

        #pragma unroll 8
        for (int j = 0; j < 64; j++) {
            float u = us[w][j];
            float nsr = fmaf(dAr, sr, fmaf(-dAi, si, dBr * u));
            float nsi = fmaf(dAi, sr, fmaf(dAr, si, dBi * u));
            sr = nsr; si = nsi;
            Sr += sr; Si += si;
        }
        __syncwarp();
    }

    float val = Cre[idx] * Sr - Cim[idx] * Si;
    val  = wredsum(val);
    usum = wredsum(usum);
    if (lane == 0)
        g_xm[b * H + h] = (2.f * val + (Dv[h] + 1.f) * usum) * (1.f / (float)L);
}

// ============ Kernel 2: head projections + parameter derivation ============
// grid (B), block 288
__global__ void k_heads(
    const float* __restrict__ writeW, const float* __restrict__ writeb,
    const float* __restrict__ readW,  const float* __restrict__ readb)
{
    __shared__ float xs[H];
    __shared__ float sow[3 * M + 6];   // 198
    __shared__ float sorh[M + 6];      // 70
    int b = blockIdx.x, t = threadIdx.x;
    if (t < H) xs[t] = g_xm[b * H + t];
    __syncthreads();

    if (t < 198) {
        float acc = writeb[t];
        for (int hh = 0; hh < H; hh++) acc = fmaf(xs[hh], writeW[hh * 198 + t], acc);
        sow[t] = acc;
    } else if (t < 268) {
        int j = t - 198;
        float acc = readb[j];
        for (int hh = 0; hh < H; hh++) acc = fmaf(xs[hh], readW[hh * 70 + j], acc);
        sorh[j] = acc;
    }
    __syncthreads();

    if (t < M) {
        g_kw[b * M + t] = sow[t];
        g_e[b * M + t]  = sigmoid_f(sow[M + 6 + t]);
        g_a[b * M + t]  = sow[2 * M + 6 + t];
        g_kr[b * M + t] = sorh[t];
    } else if (t == M) {
        float beta = softplus_f(sow[M]);
        float g    = sigmoid_f(sow[M + 1]);
        float m3 = fmaxf(sow[M + 2], fmaxf(sow[M + 3], sow[M + 4]));
        float e0 = expf(sow[M + 2] - m3), e1 = expf(sow[M + 3] - m3), e2 = expf(sow[M + 4] - m3);
        float Z = e0 + e1 + e2;
        float gamma = 1.f + softplus_f(sow[M + 5]);
        float nk = 0.f;
        for (int m = 0; m < M; m++) { float v = sow[m]; nk += v * v; }
        g_pw[b * 8 + 0] = beta; g_pw[b * 8 + 1] = g;
        g_pw[b * 8 + 2] = e0 / Z; g_pw[b * 8 + 3] = e1 / Z; g_pw[b * 8 + 4] = e2 / Z;
        g_pw[b * 8 + 5] = gamma; g_pw[b * 8 + 6] = sqrtf(nk);
    } else if (t == M + 1) {
        float beta = softplus_f(sorh[M]);
        float g    = sigmoid_f(sorh[M + 1]);
        float m3 = fmaxf(sorh[M + 2], fmaxf(sorh[M + 3], sorh[M + 4]));
        float e0 = expf(sorh[M + 2] - m3), e1 = expf(sorh[M + 3] - m3), e2 = expf(sorh[M + 4] - m3);
        float Z = e0 + e1 + e2;
        float gamma = 1.f + softplus_f(sorh[M + 5]);
        float nk = 0.f;
        for (int m = 0; m < M; m++) { float v = sorh[m]; nk += v * v; }
        g_pr[b * 8 + 0] = beta; g_pr[b * 8 + 1] = g;
        g_pr[b * 8 + 2] = e0 / Z; g_pr[b * 8 + 3] = e1 / Z; g_pr[b * 8 + 4] = e2 / Z;
        g_pr[b * 8 + 5] = gamma; g_pr[b * 8 + 6] = sqrtf(nk);
    }
}

// ============ Kernel 3: cosine-similarity scores (warp per memory row) ============
// mode 0: on mem with k_w; mode 1: on mem2 (recomputed on the fly) with k_r
// grid (B*NMEM/8), block 256
__global__ void k_score(const float* __restrict__ mem, int mode)
{
    __shared__ float ks[M], es[M], as_[M];
    int warp = threadIdx.x >> 5, lane = threadIdx.x & 31;
    int row0 = blockIdx.x * 8;
    int b = row0 >> 12;  // 4096 rows per batch, block never straddles b

    const float* kptr = mode ? (g_kr + b * M) : (g_kw + b * M);
    if (threadIdx.x < M) {
        ks[threadIdx.x] = kptr[threadIdx.x];
        if (mode) { es[threadIdx.x] = g_e[b * M + threadIdx.x]; as_[threadIdx.x] = g_a[b * M + threadIdx.x]; }
    }
    __syncthreads();

    int row = row0 + warp;
    float wv = mode ? g_ww[row] : 0.f;
    const float* mp = mem + (size_t)row * M;
    float dot = 0.f, ss = 0.f;
    #pragma unroll
    for (int q = 0; q < 2; q++) {
        int m = lane + q * 32;
        float v = mp[m];
        if (mode) v = v * (1.f - wv * es[m]) + wv * as_[m];
        dot = fmaf(v, ks[m], dot);
        ss  = fmaf(v, v, ss);
    }
    dot = wredsum(dot);
    ss  = wredsum(ss);
    if (lane == 0) {
        const float* p = mode ? g_pr : g_pw;
        float beta = p[b * 8 + 0], kn = p[b * 8 + 6];
        g_score[row] = beta * dot / (sqrtf(ss) * kn + 1e-16f);
    }
}

// ============ Kernel 4: softmax + interpolate + shift + sharpen ============
// grid (B), block 1024; mode 0: write head (prev=w_w0) -> g_ww ; mode 1: read -> g_wr
__global__ void k_address(const float* __restrict__ wprev, int mode)
{
    __shared__ float sc[NMEM];
    __shared__ float wg[NMEM];
    __shared__ float red[32];
    __shared__ float bcast;
    int b = blockIdx.x, t = threadIdx.x;
    const float* p = mode ? g_pr : g_pw;
    float g = p[b * 8 + 1], s0 = p[b * 8 + 2], s1 = p[b * 8 + 3], s2 = p[b * 8 + 4], gamma = p[b * 8 + 5];
    int lane = t & 31, w = t >> 5;

    float lm = -INFINITY;
    for (int n = t; n < NMEM; n += 1024) { float v = g_score[b * NMEM + n]; sc[n] = v; lm = fmaxf(lm, v); }
    lm = wredmax(lm);
    if (lane == 0) red[w] = lm;
    __syncthreads();
    if (w == 0) { float v = red[lane]; v = wredmax(v); if (lane == 0) bcast = v; }
    __syncthreads();
    float bm = bcast;

    float ls = 0.f;
    for (int n = t; n < NMEM; n += 1024) { float pv = expf(sc[n] - bm); sc[n] = pv; ls += pv; }
    ls = wredsum(ls);
    __syncthreads();
    if (lane == 0) red[w] = ls;
    __syncthreads();
    if (w == 0) { float v = red[lane]; v = wredsum(v); if (lane == 0) bcast = v; }
    __syncthreads();
    float Z = bcast;

    for (int n = t; n < NMEM; n += 1024)
        wg[n] = g * (sc[n] / Z) + (1.f - g) * wprev[b * NMEM + n];
    __syncthreads();

    float lp = 0.f;
    for (int n = t; n < NMEM; n += 1024) {
        float wt = s0 * wg[(n - 1) & (NMEM - 1)] + s1 * wg[n] + s2 * wg[(n + 1) & (NMEM - 1)];
        float wp = powf(wt, gamma);
        sc[n] = wp; lp += wp;
    }
    lp = wredsum(lp);
    __syncthreads();
    if (lane == 0) red[w] = lp;
    __syncthreads();
    if (w == 0) { float v = red[lane]; v = wredsum(v); if (lane == 0) bcast = v + 1e-16f; }
    __syncthreads();
    float Zp = bcast;

    float* wout = mode ? g_wr : g_ww;
    for (int n = t; n < NMEM; n += 1024) wout[b * NMEM + n] = sc[n] / Zp;
}

// ============ Kernel 5: r partials = w_r . mem2 (mem2 recomputed) ============
// grid (B, 16), block 256
__global__ void k_readvec(const float* __restrict__ mem)
{
    __shared__ float es[M], as_[M];
    __shared__ float part[4][M];
    int b = blockIdx.x, chunk = blockIdx.y;
    int t = threadIdx.x, m = t & 63, grp = t >> 6;
    if (t < M) { es[t] = g_e[b * M + t]; as_[t] = g_a[b * M + t]; }
    __syncthreads();
    float acc = 0.f;
    int n0 = chunk * 256;
    for (int n = n0 + grp; n < n0 + 256; n += 4) {
        int row = b * NMEM + n;
        float wwv = g_ww[row], wrv = g_wr[row];
        float v = mem[(size_t)row * M + m];
        float v2 = v * (1.f - wwv * es[m]) + wwv * as_[m];
        acc = fmaf(wrv, v2, acc);
    }
    part[grp][m] = acc;
    __syncthreads();
    if (grp == 0)
        g_rpart[(b * 16 + chunk) * M + m] = part[0][m] + part[1][m] + part[2][m] + part[3][m];
}

// ============ Kernel 6: decoder ============
// grid (B), block 256
__global__ void k_decode(const float* __restrict__ decW, const float* __restrict__ decb,
                         float* __restrict__ out)
{
    __shared__ float xs[H];
    __shared__ float rs[M];
    int b = blockIdx.x, t = threadIdx.x;
    xs[t] = g_xm[b * H + t];
    if (t < M) {
        float s = 0.f;
        for (int c = 0; c < 16; c++) s += g_rpart[(b * 16 + c) * M + t];
        rs[t] = s;
    }
    __syncthreads();
    if (t < OUT) {
        float acc = decb[t];
        for (int hh = 0; hh < H; hh++) acc = fmaf(xs[hh], decW[hh * OUT + t], acc);
        for (int m = 0; m < M; m++) acc = fmaf(rs[m], decW[(H + m) * OUT + t], acc);
        out[b * OUT + t] = acc;
    }
}

// ---------------- launch ----------------
extern "C" void kernel_launch(void* const* d_in, const int* in_sizes, int n_in,
                              void* d_out, int out_size)
{
    const float* x      = (const float*)d_in[0];
    const float* r0     = (const float*)d_in[1];
    const float* sr0    = (const float*)d_in[2];
    const float* si0    = (const float*)d_in[3];
    const float* w_r0   = (const float*)d_in[4];
    const float* w_w0   = (const float*)d_in[5];
    const float* mem    = (const float*)d_in[6];
    const float* encW   = (const float*)d_in[7];
    const float* encb   = (const float*)d_in[8];
    const float* log_dt = (const float*)d_in[9];
    const float* logAr  = (const float*)d_in[10];
    const float* Aim    = (const float*)d_in[11];
    const float* Cre    = (const float*)d_in[12];
    const float* Cim    = (const float*)d_in[13];
    const float* Dv     = (const float*)d_in[14];
    const float* decW   = (const float*)d_in[15];
    const float* decb   = (const float*)d_in[16];
    const float* readW  = (const float*)d_in[17];
    const float* readb  = (const float*)d_in[18];
    const float* writeW = (const float*)d_in[19];
    const float* writeb = (const float*)d_in[20];
    float* out = (float*)d_out;

    k_encode_scan<<<dim3(B, H / 8), 256>>>(x, r0, sr0, si0, encW, encb,
                                           log_dt, logAr, Aim, Cre, Cim, Dv);
    k_heads<<<B, 288>>>(writeW, writeb, readW, readb);
    k_score<<<B * NMEM / 8, 256>>>(mem, 0);
    k_address<<<B, 1024>>>(w_w0, 0);
    k_score<<<B * NMEM / 8, 256>>>(mem, 1);
    k_address<<<B, 1024>>>(w_r0, 1);
    k_readvec<<<dim3(B, 16), 256>>>(mem);
    k_decode<<<B, 256>>>(decW, decb, out);
}